// round 8
// baseline (speedup 1.0000x reference)
#include <cuda_runtime.h>
#include <cuda_fp16.h>
#include <cstdint>

#define N_TOK 8192
#define D_IN  4096
#define D_OUT 4096
#define RANK  64
#define D_PAD 4160            // D_IN + RANK

#define BM 128
#define BN 256
#define BK 64
#define NCHUNK (D_PAD / BK)   // 65
#define STAGES 4
#define THREADS 256

#define A_TILE_BYTES (BM * BK * 2)          // 16384
#define B_TILE_BYTES (BN * BK * 2)          // 32768
#define STAGE_BYTES (A_TILE_BYTES + B_TILE_BYTES)  // 49152
#define SMEM_TOTAL (STAGES * STAGE_BYTES)   // 196608

// Scratch via __device__ globals (runtime allocation is forbidden)
__device__ __half g_A[(size_t)N_TOK * D_PAD];   // [x | x@D^T] fp16   68 MB
__device__ __half g_B[(size_t)D_OUT * D_PAD];   // [Q*s | U]  fp16    34 MB
__device__ __half g_D[(size_t)RANK * D_IN];     // fp16(D)           0.5 MB

// ---------------- PTX helpers ----------------
__device__ __forceinline__ uint32_t smem_u32(const void* p) {
    uint32_t a;
    asm("{ .reg .u64 t; cvta.to.shared.u64 t, %1; cvt.u32.u64 %0, t; }" : "=r"(a) : "l"(p));
    return a;
}
__device__ __forceinline__ void cp16(uint32_t saddr, const void* g) {
    asm volatile("cp.async.cg.shared.global [%0], [%1], 16;" :: "r"(saddr), "l"(g));
}
#define CP_COMMIT() asm volatile("cp.async.commit_group;" ::: "memory")
#define CP_WAIT2()  asm volatile("cp.async.wait_group 2;" ::: "memory")

__device__ __forceinline__ void ldm_x4(uint32_t& r0, uint32_t& r1, uint32_t& r2, uint32_t& r3,
                                       uint32_t addr) {
    asm volatile("ldmatrix.sync.aligned.m8n8.x4.shared.b16 {%0,%1,%2,%3}, [%4];"
                 : "=r"(r0), "=r"(r1), "=r"(r2), "=r"(r3) : "r"(addr));
}
__device__ __forceinline__ void mma16816(float* d, const uint32_t* a, const uint32_t* b) {
    asm volatile(
        "mma.sync.aligned.m16n8k16.row.col.f32.f16.f16.f32 "
        "{%0,%1,%2,%3}, {%4,%5,%6,%7}, {%8,%9}, {%0,%1,%2,%3};"
        : "+f"(d[0]), "+f"(d[1]), "+f"(d[2]), "+f"(d[3])
        : "r"(a[0]), "r"(a[1]), "r"(a[2]), "r"(a[3]), "r"(b[0]), "r"(b[1]));
}

// ---------------- prep kernels ----------------

// x (fp32) -> g_A cols [0,4096) fp16; 8 floats/thread; 2 blocks per row
__global__ void __launch_bounds__(256) prep_a_kernel(const float* __restrict__ x) {
    int row = blockIdx.x >> 1;
    int col = ((blockIdx.x & 1) << 11) + threadIdx.x * 8;
    const float* src = x + (size_t)row * D_IN + col;
    float4 v0 = *reinterpret_cast<const float4*>(src);
    float4 v1 = *reinterpret_cast<const float4*>(src + 4);
    __half2 hv[4];
    hv[0] = __floats2half2_rn(v0.x, v0.y);
    hv[1] = __floats2half2_rn(v0.z, v0.w);
    hv[2] = __floats2half2_rn(v1.x, v1.y);
    hv[3] = __floats2half2_rn(v1.z, v1.w);
    *reinterpret_cast<uint4*>(g_A + (size_t)row * D_PAD + col) = *reinterpret_cast<uint4*>(hv);
}

// D (fp32 [64,4096]) -> g_D fp16
__global__ void __launch_bounds__(256) conv_d_kernel(const float* __restrict__ Dm) {
    size_t i = (size_t)blockIdx.x * 1024 + threadIdx.x * 4;
    float4 v = *reinterpret_cast<const float4*>(Dm + i);
    __half2 h0 = __floats2half2_rn(v.x, v.y);
    __half2 h1 = __floats2half2_rn(v.z, v.w);
    uint2 st;
    st.x = *reinterpret_cast<uint32_t*>(&h0);
    st.y = *reinterpret_cast<uint32_t*>(&h1);
    *reinterpret_cast<uint2*>(g_D + i) = st;
}

// U (fp32 [4096,64]) -> g_B cols [4096,4160) fp16
__global__ void __launch_bounds__(256) copy_u_kernel(const float* __restrict__ U) {
    size_t i = (size_t)blockIdx.x * 512 + threadIdx.x * 2;  // element pairs
    int o = (int)(i >> 6);
    int r = (int)(i & 63);
    float2 v = *reinterpret_cast<const float2*>(U + i);
    __half2 h = __floats2half2_rn(v.x, v.y);
    *reinterpret_cast<__half2*>(g_B + (size_t)o * D_PAD + D_IN + r) = h;
}

// pure dequant: g_B[o, i] = fp16(Q[o,i] * scales[o]); 8 elems/thread; 2 blocks/row
__global__ void __launch_bounds__(256) prep_w_kernel(
    const float* __restrict__ scales, const int* __restrict__ Q)
{
    int o = blockIdx.x >> 1;
    int col = ((blockIdx.x & 1) << 11) + threadIdx.x * 8;
    float sc = scales[o];
    const int* src = Q + (size_t)o * D_IN + col;
    int4 q0 = *reinterpret_cast<const int4*>(src);
    int4 q1 = *reinterpret_cast<const int4*>(src + 4);
    __half2 hv[4];
    hv[0] = __floats2half2_rn((float)q0.x * sc, (float)q0.y * sc);
    hv[1] = __floats2half2_rn((float)q0.z * sc, (float)q0.w * sc);
    hv[2] = __floats2half2_rn((float)q1.x * sc, (float)q1.y * sc);
    hv[3] = __floats2half2_rn((float)q1.z * sc, (float)q1.w * sc);
    *reinterpret_cast<uint4*>(g_B + (size_t)o * D_PAD + col) = *reinterpret_cast<uint4*>(hv);
}

// ---------------- adapter GEMM: T = x @ D^T  -> g_A cols [4096,4160) ----------------
// M=8192, N=64, K=4096. BM=64, BN=64, BK=64, 128 threads (4 warps 2x2, warp 32x32).
#define AD_STAGE_BYTES (2 * 64 * 128)        // A 8KB + B 8KB
#define AD_SMEM (STAGES * AD_STAGE_BYTES)    // 65536
__global__ void __launch_bounds__(128, 1) adapter_kernel() {
    extern __shared__ char smem[];
    uint32_t sbase = smem_u32(smem);
    int tid = threadIdx.x;
    int wid = tid >> 5;
    int lane = tid & 31;
    int m0 = blockIdx.x * 64;
    int wm = wid & 1;   // 32-row half
    int wn = wid >> 1;  // 32-col half

    auto load_stage = [&](int s, int c) {
        uint32_t st = sbase + s * AD_STAGE_BYTES;
        int k0 = c * BK;
#pragma unroll
        for (int j = 0; j < 4; ++j) {  // A: 512 chunks
            int t = tid + j * 128;
            int row = t >> 3, seg = t & 7;
            uint32_t so = (uint32_t)(row * 128 + ((seg ^ (row & 7)) << 4));
            cp16(st + so, g_A + (size_t)(m0 + row) * D_PAD + k0 + seg * 8);
        }
#pragma unroll
        for (int j = 0; j < 4; ++j) {  // B (D): 512 chunks
            int t = tid + j * 128;
            int row = t >> 3, seg = t & 7;
            uint32_t so = (uint32_t)(row * 128 + ((seg ^ (row & 7)) << 4));
            cp16(st + 8192 + so, g_D + (size_t)row * D_IN + k0 + seg * 8);
        }
    };

#pragma unroll
    for (int s = 0; s < STAGES - 1; ++s) { load_stage(s, s); CP_COMMIT(); }

    float acc[2][4][4] = {};
    int a_row_base = wm * 32 + (lane & 15);
    int b_row_base = wn * 32 + (lane & 15);
    int hi = lane >> 4;

    for (int c = 0; c < 64; ++c) {
        CP_WAIT2();
        __syncthreads();
        if (c + STAGES - 1 < 64) load_stage((c + STAGES - 1) & (STAGES - 1), c + STAGES - 1);
        CP_COMMIT();

        uint32_t stA = sbase + (c & (STAGES - 1)) * AD_STAGE_BYTES;
        uint32_t stB = stA + 8192;
#pragma unroll
        for (int kt = 0; kt < 4; ++kt) {
            uint32_t af[2][4];
#pragma unroll
            for (int mi = 0; mi < 2; ++mi) {
                int row = a_row_base + mi * 16;
                uint32_t chunk = (uint32_t)((kt * 2 + hi) ^ (row & 7));
                ldm_x4(af[mi][0], af[mi][1], af[mi][2], af[mi][3],
                       stA + (uint32_t)row * 128 + (chunk << 4));
            }
            uint32_t bf[4][2];
#pragma unroll
            for (int nj = 0; nj < 2; ++nj) {
                int row = b_row_base + nj * 16;
                uint32_t chunk = (uint32_t)((kt * 2 + hi) ^ (row & 7));
                uint32_t r0, r1, r2, r3;
                ldm_x4(r0, r1, r2, r3, stB + (uint32_t)row * 128 + (chunk << 4));
                bf[nj * 2][0] = r0; bf[nj * 2][1] = r2;
                bf[nj * 2 + 1][0] = r1; bf[nj * 2 + 1][1] = r3;
            }
#pragma unroll
            for (int mi = 0; mi < 2; ++mi)
#pragma unroll
                for (int ni = 0; ni < 4; ++ni)
                    mma16816(acc[mi][ni], af[mi], bf[ni]);
        }
    }

    // store fp16 into g_A cols [4096, 4160)
    int row0 = m0 + wm * 32 + (lane >> 2);
    int colb = wn * 32 + (lane & 3) * 2;
#pragma unroll
    for (int mi = 0; mi < 2; ++mi) {
#pragma unroll
        for (int ni = 0; ni < 4; ++ni) {
            __half2 h0 = __floats2half2_rn(acc[mi][ni][0], acc[mi][ni][1]);
            __half2 h1 = __floats2half2_rn(acc[mi][ni][2], acc[mi][ni][3]);
            *reinterpret_cast<__half2*>(
                g_A + (size_t)(row0 + mi * 16) * D_PAD + D_IN + colb + ni * 8) = h0;
            *reinterpret_cast<__half2*>(
                g_A + (size_t)(row0 + mi * 16 + 8) * D_PAD + D_IN + colb + ni * 8) = h1;
        }
    }
}

// ---------------- main GEMM ----------------
// out[m,n] = sum_k g_A[m,k] * g_B[n,k] over K=4160; fp16 in, fp32 accum.
// BM=128, BN=256, BK=64, 4-stage cp.async, mma.sync m16n8k16.
// 8 warps in 2x4; each warp owns 64x64 (4 m16 x 8 n8), fragments double-buffered over kt.
__global__ void __launch_bounds__(THREADS, 1) gemm_kernel(float* __restrict__ out) {
    extern __shared__ char smem[];
    uint32_t sbase = smem_u32(smem);
    int tid = threadIdx.x;
    int wid = tid >> 5;
    int lane = tid & 31;

    int bx = blockIdx.x;
    int band = bx >> 8;
    int r = bx & 255;
    int n_tile = r >> 4;
    int m_tile = (band << 4) + (r & 15);
    int m0 = m_tile * BM;
    int n0 = n_tile * BN;

    int wm = wid & 1;   // 64-row half
    int wn = wid >> 1;  // 64-col quarter

    auto load_stage = [&](int s, int c) {
        uint32_t st = sbase + s * STAGE_BYTES;
        int k0 = c * BK;
#pragma unroll
        for (int j = 0; j < 4; ++j) {  // A: 1024 chunks
            int t = tid + j * THREADS;
            int row = t >> 3, seg = t & 7;
            uint32_t so = (uint32_t)(row * 128 + ((seg ^ (row & 7)) << 4));
            cp16(st + so, g_A + (size_t)(m0 + row) * D_PAD + k0 + seg * 8);
        }
#pragma unroll
        for (int j = 0; j < 8; ++j) {  // B: 2048 chunks
            int t = tid + j * THREADS;
            int row = t >> 3, seg = t & 7;
            uint32_t so = (uint32_t)(row * 128 + ((seg ^ (row & 7)) << 4));
            cp16(st + A_TILE_BYTES + so, g_B + (size_t)(n0 + row) * D_PAD + k0 + seg * 8);
        }
    };

#pragma unroll
    for (int s = 0; s < STAGES - 1; ++s) { load_stage(s, s); CP_COMMIT(); }

    float acc[4][8][4] = {};            // [mi][ni][4]
    uint32_t af[2][4][4];               // [buf][mi][4]
    uint32_t bf[2][8][2];               // [buf][ni][2]

    int a_row_base = wm * 64 + (lane & 15);
    int b_row_base = wn * 64 + (lane & 15);
    int hi = lane >> 4;

    // fragment loader for one kt into buffer `bu`
    auto load_frags = [&](uint32_t stA, uint32_t stB, int kt, int bu) {
#pragma unroll
        for (int mi = 0; mi < 4; ++mi) {
            int row = a_row_base + mi * 16;
            uint32_t chunk = (uint32_t)((kt * 2 + hi) ^ (row & 7));
            ldm_x4(af[bu][mi][0], af[bu][mi][1], af[bu][mi][2], af[bu][mi][3],
                   stA + (uint32_t)row * 128 + (chunk << 4));
        }
#pragma unroll
        for (int nj = 0; nj < 4; ++nj) {
            int row = b_row_base + nj * 16;
            uint32_t chunk = (uint32_t)((kt * 2 + hi) ^ (row & 7));
            uint32_t r0, r1, r2, r3;
            ldm_x4(r0, r1, r2, r3, stB + (uint32_t)row * 128 + (chunk << 4));
            bf[bu][nj * 2][0] = r0; bf[bu][nj * 2][1] = r2;
            bf[bu][nj * 2 + 1][0] = r1; bf[bu][nj * 2 + 1][1] = r3;
        }
    };

    for (int c = 0; c < NCHUNK; ++c) {
        CP_WAIT2();
        __syncthreads();
        if (c + STAGES - 1 < NCHUNK) load_stage((c + STAGES - 1) & (STAGES - 1), c + STAGES - 1);
        CP_COMMIT();

        uint32_t stA = sbase + (c & (STAGES - 1)) * STAGE_BYTES;
        uint32_t stB = stA + A_TILE_BYTES;

        load_frags(stA, stB, 0, 0);
#pragma unroll
        for (int kt = 0; kt < 4; ++kt) {
            int cur = kt & 1;
            if (kt < 3) load_frags(stA, stB, kt + 1, cur ^ 1);
#pragma unroll
            for (int mi = 0; mi < 4; ++mi)
#pragma unroll
                for (int ni = 0; ni < 8; ++ni)
                    mma16816(acc[mi][ni], af[cur][mi], bf[cur][ni]);
        }
    }

    // Epilogue: direct float2 stores
    {
        int row0 = m0 + wm * 64 + (lane >> 2);
        int colb = n0 + wn * 64 + (lane & 3) * 2;
#pragma unroll
        for (int mi = 0; mi < 4; ++mi) {
#pragma unroll
            for (int ni = 0; ni < 8; ++ni) {
                float* p0 = out + (size_t)(row0 + mi * 16) * D_OUT + colb + ni * 8;
                float* p1 = out + (size_t)(row0 + mi * 16 + 8) * D_OUT + colb + ni * 8;
                float2 v0 = {acc[mi][ni][0], acc[mi][ni][1]};
                float2 v1 = {acc[mi][ni][2], acc[mi][ni][3]};
                *reinterpret_cast<float2*>(p0) = v0;
                *reinterpret_cast<float2*>(p1) = v1;
            }
        }
    }
}

// ---------------- launch ----------------
extern "C" void kernel_launch(void* const* d_in, const int* in_sizes, int n_in,
                              void* d_out, int out_size) {
    const float* x      = (const float*)d_in[0];
    const float* scales = (const float*)d_in[1];
    const float* U      = (const float*)d_in[2];
    const float* Dm     = (const float*)d_in[3];
    const int*   Q      = (const int*)d_in[4];
    float* out = (float*)d_out;

    cudaFuncSetAttribute(gemm_kernel, cudaFuncAttributeMaxDynamicSharedMemorySize, SMEM_TOTAL);
    cudaFuncSetAttribute(adapter_kernel, cudaFuncAttributeMaxDynamicSharedMemorySize, AD_SMEM);

    prep_a_kernel<<<N_TOK * 2, 256>>>(x);
    conv_d_kernel<<<(RANK * D_IN) / 1024, 256>>>(Dm);
    adapter_kernel<<<N_TOK / 64, 128, AD_SMEM>>>();
    prep_w_kernel<<<D_OUT * 2, 256>>>(scales, Q);
    copy_u_kernel<<<(D_OUT * RANK) / 512, 256>>>(U);
    gemm_kernel<<<(N_TOK / BM) * (D_OUT / BN), THREADS, SMEM_TOTAL>>>(out);
}

// round 9
// speedup vs baseline: 1.2228x; 1.2228x over previous
#include <cuda_runtime.h>
#include <cuda_fp16.h>
#include <cstdint>

#define N_TOK 8192
#define D_IN  4096
#define D_OUT 4096
#define RANK  64
#define D_PAD 4160            // D_IN + RANK

#define BM 128
#define BN 256
#define BK 64
#define NCHUNK (D_PAD / BK)   // 65
#define STAGES 4
#define THREADS 256

#define A_TILE_BYTES (BM * BK * 2)          // 16384
#define B_TILE_BYTES (BN * BK * 2)          // 32768
#define STAGE_BYTES (A_TILE_BYTES + B_TILE_BYTES)  // 49152
#define SMEM_TOTAL (STAGES * STAGE_BYTES)   // 196608

// Scratch via __device__ globals (runtime allocation is forbidden)
__device__ __half g_A[(size_t)N_TOK * D_PAD];   // [x | x@D^T] fp16   68 MB
__device__ __half g_B[(size_t)D_OUT * D_PAD];   // [Q*s | U]  fp16    34 MB
__device__ __half g_D[(size_t)RANK * D_IN];     // fp16(D)           0.5 MB

// ---------------- PTX helpers ----------------
__device__ __forceinline__ uint32_t smem_u32(const void* p) {
    uint32_t a;
    asm("{ .reg .u64 t; cvta.to.shared.u64 t, %1; cvt.u32.u64 %0, t; }" : "=r"(a) : "l"(p));
    return a;
}
__device__ __forceinline__ void cp16(uint32_t saddr, const void* g) {
    asm volatile("cp.async.cg.shared.global [%0], [%1], 16;" :: "r"(saddr), "l"(g));
}
#define CP_COMMIT() asm volatile("cp.async.commit_group;" ::: "memory")
#define CP_WAIT1()  asm volatile("cp.async.wait_group 1;" ::: "memory")
#define CP_WAIT2()  asm volatile("cp.async.wait_group 2;" ::: "memory")

__device__ __forceinline__ void ldm_x4(uint32_t& r0, uint32_t& r1, uint32_t& r2, uint32_t& r3,
                                       uint32_t addr) {
    asm volatile("ldmatrix.sync.aligned.m8n8.x4.shared.b16 {%0,%1,%2,%3}, [%4];"
                 : "=r"(r0), "=r"(r1), "=r"(r2), "=r"(r3) : "r"(addr));
}
__device__ __forceinline__ void mma16816(float* d, const uint32_t* a, const uint32_t* b) {
    asm volatile(
        "mma.sync.aligned.m16n8k16.row.col.f32.f16.f16.f32 "
        "{%0,%1,%2,%3}, {%4,%5,%6,%7}, {%8,%9}, {%0,%1,%2,%3};"
        : "+f"(d[0]), "+f"(d[1]), "+f"(d[2]), "+f"(d[3])
        : "r"(a[0]), "r"(a[1]), "r"(a[2]), "r"(a[3]), "r"(b[0]), "r"(b[1]));
}

// ---------------- prep kernels ----------------

// x (fp32) -> g_A cols [0,4096) fp16; 8 floats/thread; 2 blocks per row
__global__ void __launch_bounds__(256) prep_a_kernel(const float* __restrict__ x) {
    int row = blockIdx.x >> 1;
    int col = ((blockIdx.x & 1) << 11) + threadIdx.x * 8;
    const float* src = x + (size_t)row * D_IN + col;
    float4 v0 = *reinterpret_cast<const float4*>(src);
    float4 v1 = *reinterpret_cast<const float4*>(src + 4);
    __half2 hv[4];
    hv[0] = __floats2half2_rn(v0.x, v0.y);
    hv[1] = __floats2half2_rn(v0.z, v0.w);
    hv[2] = __floats2half2_rn(v1.x, v1.y);
    hv[3] = __floats2half2_rn(v1.z, v1.w);
    *reinterpret_cast<uint4*>(g_A + (size_t)row * D_PAD + col) = *reinterpret_cast<uint4*>(hv);
}

// D (fp32 [64,4096]) -> g_D fp16
__global__ void __launch_bounds__(256) conv_d_kernel(const float* __restrict__ Dm) {
    size_t i = (size_t)blockIdx.x * 1024 + threadIdx.x * 4;
    float4 v = *reinterpret_cast<const float4*>(Dm + i);
    __half2 h0 = __floats2half2_rn(v.x, v.y);
    __half2 h1 = __floats2half2_rn(v.z, v.w);
    uint2 st;
    st.x = *reinterpret_cast<uint32_t*>(&h0);
    st.y = *reinterpret_cast<uint32_t*>(&h1);
    *reinterpret_cast<uint2*>(g_D + i) = st;
}

// U (fp32 [4096,64]) -> g_B cols [4096,4160) fp16
__global__ void __launch_bounds__(256) copy_u_kernel(const float* __restrict__ U) {
    size_t i = (size_t)blockIdx.x * 512 + threadIdx.x * 2;  // element pairs
    int o = (int)(i >> 6);
    int r = (int)(i & 63);
    float2 v = *reinterpret_cast<const float2*>(U + i);
    __half2 h = __floats2half2_rn(v.x, v.y);
    *reinterpret_cast<__half2*>(g_B + (size_t)o * D_PAD + D_IN + r) = h;
}

// pure dequant: g_B[o, i] = fp16(Q[o,i] * scales[o]); 8 elems/thread; 2 blocks/row
__global__ void __launch_bounds__(256) prep_w_kernel(
    const float* __restrict__ scales, const int* __restrict__ Q)
{
    int o = blockIdx.x >> 1;
    int col = ((blockIdx.x & 1) << 11) + threadIdx.x * 8;
    float sc = scales[o];
    const int* src = Q + (size_t)o * D_IN + col;
    int4 q0 = *reinterpret_cast<const int4*>(src);
    int4 q1 = *reinterpret_cast<const int4*>(src + 4);
    __half2 hv[4];
    hv[0] = __floats2half2_rn((float)q0.x * sc, (float)q0.y * sc);
    hv[1] = __floats2half2_rn((float)q0.z * sc, (float)q0.w * sc);
    hv[2] = __floats2half2_rn((float)q1.x * sc, (float)q1.y * sc);
    hv[3] = __floats2half2_rn((float)q1.z * sc, (float)q1.w * sc);
    *reinterpret_cast<uint4*>(g_B + (size_t)o * D_PAD + col) = *reinterpret_cast<uint4*>(hv);
}

// ---------------- adapter GEMM: T = x @ D^T  -> g_A cols [4096,4160) ----------------
#define AD_STAGE_BYTES (2 * 64 * 128)        // A 8KB + B 8KB
#define AD_SMEM (STAGES * AD_STAGE_BYTES)    // 65536
__global__ void __launch_bounds__(128, 1) adapter_kernel() {
    extern __shared__ char smem[];
    uint32_t sbase = smem_u32(smem);
    int tid = threadIdx.x;
    int wid = tid >> 5;
    int lane = tid & 31;
    int m0 = blockIdx.x * 64;
    int wm = wid & 1;
    int wn = wid >> 1;

    auto load_stage = [&](int s, int c) {
        uint32_t st = sbase + s * AD_STAGE_BYTES;
        int k0 = c * BK;
#pragma unroll
        for (int j = 0; j < 4; ++j) {
            int t = tid + j * 128;
            int row = t >> 3, seg = t & 7;
            uint32_t so = (uint32_t)(row * 128 + ((seg ^ (row & 7)) << 4));
            cp16(st + so, g_A + (size_t)(m0 + row) * D_PAD + k0 + seg * 8);
        }
#pragma unroll
        for (int j = 0; j < 4; ++j) {
            int t = tid + j * 128;
            int row = t >> 3, seg = t & 7;
            uint32_t so = (uint32_t)(row * 128 + ((seg ^ (row & 7)) << 4));
            cp16(st + 8192 + so, g_D + (size_t)row * D_IN + k0 + seg * 8);
        }
    };

#pragma unroll
    for (int s = 0; s < STAGES - 1; ++s) { load_stage(s, s); CP_COMMIT(); }

    float acc[2][4][4] = {};
    int a_row_base = wm * 32 + (lane & 15);
    int b_row_base = wn * 32 + (lane & 15);
    int hi = lane >> 4;

    for (int c = 0; c < 64; ++c) {
        CP_WAIT2();
        __syncthreads();
        if (c + STAGES - 1 < 64) load_stage((c + STAGES - 1) & (STAGES - 1), c + STAGES - 1);
        CP_COMMIT();

        uint32_t stA = sbase + (c & (STAGES - 1)) * AD_STAGE_BYTES;
        uint32_t stB = stA + 8192;
#pragma unroll
        for (int kt = 0; kt < 4; ++kt) {
            uint32_t af[2][4];
#pragma unroll
            for (int mi = 0; mi < 2; ++mi) {
                int row = a_row_base + mi * 16;
                uint32_t chunk = (uint32_t)((kt * 2 + hi) ^ (row & 7));
                ldm_x4(af[mi][0], af[mi][1], af[mi][2], af[mi][3],
                       stA + (uint32_t)row * 128 + (chunk << 4));
            }
            uint32_t bf[4][2];
#pragma unroll
            for (int nj = 0; nj < 2; ++nj) {
                int row = b_row_base + nj * 16;
                uint32_t chunk = (uint32_t)((kt * 2 + hi) ^ (row & 7));
                uint32_t r0, r1, r2, r3;
                ldm_x4(r0, r1, r2, r3, stB + (uint32_t)row * 128 + (chunk << 4));
                bf[nj * 2][0] = r0; bf[nj * 2][1] = r2;
                bf[nj * 2 + 1][0] = r1; bf[nj * 2 + 1][1] = r3;
            }
#pragma unroll
            for (int mi = 0; mi < 2; ++mi)
#pragma unroll
                for (int ni = 0; ni < 4; ++ni)
                    mma16816(acc[mi][ni], af[mi], bf[ni]);
        }
    }

    int row0 = m0 + wm * 32 + (lane >> 2);
    int colb = wn * 32 + (lane & 3) * 2;
#pragma unroll
    for (int mi = 0; mi < 2; ++mi) {
#pragma unroll
        for (int ni = 0; ni < 4; ++ni) {
            __half2 h0 = __floats2half2_rn(acc[mi][ni][0], acc[mi][ni][1]);
            __half2 h1 = __floats2half2_rn(acc[mi][ni][2], acc[mi][ni][3]);
            *reinterpret_cast<__half2*>(
                g_A + (size_t)(row0 + mi * 16) * D_PAD + D_IN + colb + ni * 8) = h0;
            *reinterpret_cast<__half2*>(
                g_A + (size_t)(row0 + mi * 16 + 8) * D_PAD + D_IN + colb + ni * 8) = h1;
        }
    }
}

// ---------------- main GEMM ----------------
// out[m,n] = sum_k g_A[m,k] * g_B[n,k] over K=4160; fp16 in, fp32 accum.
// BM=128, BN=256, BK=64, 4-stage cp.async. 8 warps (2x4), warp tile 64x64.
// Software-pipelined: fragments double-buffered, mid-chunk wait/sync,
// next-chunk kt0 fragments prefetched during kt3.
__global__ void __launch_bounds__(THREADS, 1) gemm_kernel(float* __restrict__ out) {
    extern __shared__ char smem[];
    uint32_t sbase = smem_u32(smem);
    int tid = threadIdx.x;
    int wid = tid >> 5;
    int lane = tid & 31;

    int bx = blockIdx.x;
    int band = bx >> 8;
    int r = bx & 255;
    int n_tile = r >> 4;
    int m_tile = (band << 4) + (r & 15);
    int m0 = m_tile * BM;
    int n0 = n_tile * BN;

    int wm = wid & 1;   // 64-row half
    int wn = wid >> 1;  // 64-col quarter

    auto load_stage = [&](int s, int c) {
        uint32_t st = sbase + s * STAGE_BYTES;
        int k0 = c * BK;
#pragma unroll
        for (int j = 0; j < 4; ++j) {  // A: 1024 chunks
            int t = tid + j * THREADS;
            int row = t >> 3, seg = t & 7;
            uint32_t so = (uint32_t)(row * 128 + ((seg ^ (row & 7)) << 4));
            cp16(st + so, g_A + (size_t)(m0 + row) * D_PAD + k0 + seg * 8);
        }
#pragma unroll
        for (int j = 0; j < 8; ++j) {  // B: 2048 chunks
            int t = tid + j * THREADS;
            int row = t >> 3, seg = t & 7;
            uint32_t so = (uint32_t)(row * 128 + ((seg ^ (row & 7)) << 4));
            cp16(st + A_TILE_BYTES + so, g_B + (size_t)(n0 + row) * D_PAD + k0 + seg * 8);
        }
    };

    float acc[4][8][4] = {};            // [mi][ni][4]
    uint32_t af[2][4][4];               // [buf][mi][4]
    uint32_t bf[2][8][2];               // [buf][ni][2]

    int a_row_base = wm * 64 + (lane & 15);
    int b_row_base = wn * 64 + (lane & 15);
    int hi = lane >> 4;

    auto load_frags = [&](uint32_t stg, int kt, int bu) {
        uint32_t stA = stg, stB = stg + A_TILE_BYTES;
#pragma unroll
        for (int mi = 0; mi < 4; ++mi) {
            int row = a_row_base + mi * 16;
            uint32_t chunk = (uint32_t)((kt * 2 + hi) ^ (row & 7));
            ldm_x4(af[bu][mi][0], af[bu][mi][1], af[bu][mi][2], af[bu][mi][3],
                   stA + (uint32_t)row * 128 + (chunk << 4));
        }
#pragma unroll
        for (int nj = 0; nj < 4; ++nj) {
            int row = b_row_base + nj * 16;
            uint32_t chunk = (uint32_t)((kt * 2 + hi) ^ (row & 7));
            uint32_t r0, r1, r2, r3;
            ldm_x4(r0, r1, r2, r3, stB + (uint32_t)row * 128 + (chunk << 4));
            bf[bu][nj * 2][0] = r0; bf[bu][nj * 2][1] = r2;
            bf[bu][nj * 2 + 1][0] = r1; bf[bu][nj * 2 + 1][1] = r3;
        }
    };

    auto mma_all = [&](int bu) {
#pragma unroll
        for (int mi = 0; mi < 4; ++mi)
#pragma unroll
            for (int ni = 0; ni < 8; ++ni)
                mma16816(acc[mi][ni], af[bu][mi], bf[bu][ni]);
    };

    // Prologue: stages 0..2 in flight; stage 0 ready; kt0 frags in buf0.
#pragma unroll
    for (int s = 0; s < STAGES - 1; ++s) { load_stage(s, s); CP_COMMIT(); }
    CP_WAIT2();                 // stage 0 complete
    __syncthreads();
    load_frags(sbase, 0, 0);

    for (int c = 0; c < NCHUNK; ++c) {
        uint32_t stC = sbase + (uint32_t)(c & (STAGES - 1)) * STAGE_BYTES;
        uint32_t stN = sbase + (uint32_t)((c + 1) & (STAGES - 1)) * STAGE_BYTES;

        // kt0: prefetch kt1 -> buf1; mma buf0
        load_frags(stC, 1, 1);
        mma_all(0);

        // kt1: prefetch kt2 -> buf0; mma buf1
        load_frags(stC, 2, 0);
        mma_all(1);

        // kt2: drain to make stage c+1 visible; then refill pipeline.
        CP_WAIT1();             // group for stage c+1 complete
        __syncthreads();        // its data visible to all threads; stage (c+3)&3 free
        load_frags(stC, 3, 1);  // kt3 frags (stage c, resident)
        mma_all(0);             // kt2
        if (c + 3 < NCHUNK) load_stage((c + 3) & (STAGES - 1), c + 3);
        CP_COMMIT();

        // kt3: prefetch next chunk's kt0 from stage c+1; mma buf1
        load_frags(stN, 0, 0);  // safe even at c == NCHUNK-1 (unused, in-bounds)
        mma_all(1);             // kt3
    }

    // Epilogue: direct float2 stores
    {
        int row0 = m0 + wm * 64 + (lane >> 2);
        int colb = n0 + wn * 64 + (lane & 3) * 2;
#pragma unroll
        for (int mi = 0; mi < 4; ++mi) {
#pragma unroll
            for (int ni = 0; ni < 8; ++ni) {
                float* p0 = out + (size_t)(row0 + mi * 16) * D_OUT + colb + ni * 8;
                float* p1 = out + (size_t)(row0 + mi * 16 + 8) * D_OUT + colb + ni * 8;
                float2 v0 = {acc[mi][ni][0], acc[mi][ni][1]};
                float2 v1 = {acc[mi][ni][2], acc[mi][ni][3]};
                *reinterpret_cast<float2*>(p0) = v0;
                *reinterpret_cast<float2*>(p1) = v1;
            }
        }
    }
}

// ---------------- launch ----------------
extern "C" void kernel_launch(void* const* d_in, const int* in_sizes, int n_in,
                              void* d_out, int out_size) {
    const float* x      = (const float*)d_in[0];
    const float* scales = (const float*)d_in[1];
    const float* U      = (const float*)d_in[2];
    const float* Dm     = (const float*)d_in[3];
    const int*   Q      = (const int*)d_in[4];
    float* out = (float*)d_out;

    cudaFuncSetAttribute(gemm_kernel, cudaFuncAttributeMaxDynamicSharedMemorySize, SMEM_TOTAL);
    cudaFuncSetAttribute(adapter_kernel, cudaFuncAttributeMaxDynamicSharedMemorySize, AD_SMEM);

    prep_a_kernel<<<N_TOK * 2, 256>>>(x);
    conv_d_kernel<<<(RANK * D_IN) / 1024, 256>>>(Dm);
    adapter_kernel<<<N_TOK / 64, 128, AD_SMEM>>>();
    prep_w_kernel<<<D_OUT * 2, 256>>>(scales, Q);
    copy_u_kernel<<<(D_OUT * RANK) / 512, 256>>>(U);
    gemm_kernel<<<(N_TOK / BM) * (D_OUT / BN), THREADS, SMEM_TOTAL>>>(out);
}

// round 10
// speedup vs baseline: 1.2361x; 1.0108x over previous
#include <cuda_runtime.h>
#include <cuda_fp16.h>
#include <cstdint>

#define N_TOK 8192
#define D_IN  4096
#define D_OUT 4096
#define RANK  64
#define D_PAD 4160            // D_IN + RANK

#define BM 128
#define BN 256
#define BK 64
#define NCHUNK (D_PAD / BK)   // 65
#define NTILES ((N_TOK / BM) * (D_OUT / BN))  // 2048
#define STAGES 4
#define THREADS 256

#define A_TILE_BYTES (BM * BK * 2)          // 16384
#define B_TILE_BYTES (BN * BK * 2)          // 32768
#define STAGE_BYTES (A_TILE_BYTES + B_TILE_BYTES)  // 49152
#define SMEM_TOTAL (STAGES * STAGE_BYTES)   // 196608

// Scratch via __device__ globals (runtime allocation is forbidden)
__device__ __half g_A[(size_t)N_TOK * D_PAD];   // [x | x@D^T] fp16   68 MB
__device__ __half g_B[(size_t)D_OUT * D_PAD];   // [Q*s | U]  fp16    34 MB
__device__ __half g_D[(size_t)RANK * D_IN];     // fp16(D)           0.5 MB

// ---------------- PTX helpers ----------------
__device__ __forceinline__ uint32_t smem_u32(const void* p) {
    uint32_t a;
    asm("{ .reg .u64 t; cvta.to.shared.u64 t, %1; cvt.u32.u64 %0, t; }" : "=r"(a) : "l"(p));
    return a;
}
__device__ __forceinline__ void cp16(uint32_t saddr, const void* g) {
    asm volatile("cp.async.cg.shared.global [%0], [%1], 16;" :: "r"(saddr), "l"(g));
}
#define CP_COMMIT() asm volatile("cp.async.commit_group;" ::: "memory")
#define CP_WAIT1()  asm volatile("cp.async.wait_group 1;" ::: "memory")
#define CP_WAIT2()  asm volatile("cp.async.wait_group 2;" ::: "memory")

__device__ __forceinline__ void ldm_x4(uint32_t& r0, uint32_t& r1, uint32_t& r2, uint32_t& r3,
                                       uint32_t addr) {
    asm volatile("ldmatrix.sync.aligned.m8n8.x4.shared.b16 {%0,%1,%2,%3}, [%4];"
                 : "=r"(r0), "=r"(r1), "=r"(r2), "=r"(r3) : "r"(addr));
}
__device__ __forceinline__ void mma16816(float* d, const uint32_t* a, const uint32_t* b) {
    asm volatile(
        "mma.sync.aligned.m16n8k16.row.col.f32.f16.f16.f32 "
        "{%0,%1,%2,%3}, {%4,%5,%6,%7}, {%8,%9}, {%0,%1,%2,%3};"
        : "+f"(d[0]), "+f"(d[1]), "+f"(d[2]), "+f"(d[3])
        : "r"(a[0]), "r"(a[1]), "r"(a[2]), "r"(a[3]), "r"(b[0]), "r"(b[1]));
}

// ---------------- prep kernels ----------------

// x (fp32) -> g_A cols [0,4096) fp16; 8 floats/thread; 2 blocks per row
__global__ void __launch_bounds__(256) prep_a_kernel(const float* __restrict__ x) {
    int row = blockIdx.x >> 1;
    int col = ((blockIdx.x & 1) << 11) + threadIdx.x * 8;
    const float* src = x + (size_t)row * D_IN + col;
    float4 v0 = *reinterpret_cast<const float4*>(src);
    float4 v1 = *reinterpret_cast<const float4*>(src + 4);
    __half2 hv[4];
    hv[0] = __floats2half2_rn(v0.x, v0.y);
    hv[1] = __floats2half2_rn(v0.z, v0.w);
    hv[2] = __floats2half2_rn(v1.x, v1.y);
    hv[3] = __floats2half2_rn(v1.z, v1.w);
    *reinterpret_cast<uint4*>(g_A + (size_t)row * D_PAD + col) = *reinterpret_cast<uint4*>(hv);
}

// D (fp32 [64,4096]) -> g_D fp16
__global__ void __launch_bounds__(256) conv_d_kernel(const float* __restrict__ Dm) {
    size_t i = (size_t)blockIdx.x * 1024 + threadIdx.x * 4;
    float4 v = *reinterpret_cast<const float4*>(Dm + i);
    __half2 h0 = __floats2half2_rn(v.x, v.y);
    __half2 h1 = __floats2half2_rn(v.z, v.w);
    uint2 st;
    st.x = *reinterpret_cast<uint32_t*>(&h0);
    st.y = *reinterpret_cast<uint32_t*>(&h1);
    *reinterpret_cast<uint2*>(g_D + i) = st;
}

// U (fp32 [4096,64]) -> g_B cols [4096,4160) fp16
__global__ void __launch_bounds__(256) copy_u_kernel(const float* __restrict__ U) {
    size_t i = (size_t)blockIdx.x * 512 + threadIdx.x * 2;  // element pairs
    int o = (int)(i >> 6);
    int r = (int)(i & 63);
    float2 v = *reinterpret_cast<const float2*>(U + i);
    __half2 h = __floats2half2_rn(v.x, v.y);
    *reinterpret_cast<__half2*>(g_B + (size_t)o * D_PAD + D_IN + r) = h;
}

// pure dequant: g_B[o, i] = fp16(Q[o,i] * scales[o]); 8 elems/thread; 2 blocks/row
__global__ void __launch_bounds__(256) prep_w_kernel(
    const float* __restrict__ scales, const int* __restrict__ Q)
{
    int o = blockIdx.x >> 1;
    int col = ((blockIdx.x & 1) << 11) + threadIdx.x * 8;
    float sc = scales[o];
    const int* src = Q + (size_t)o * D_IN + col;
    int4 q0 = *reinterpret_cast<const int4*>(src);
    int4 q1 = *reinterpret_cast<const int4*>(src + 4);
    __half2 hv[4];
    hv[0] = __floats2half2_rn((float)q0.x * sc, (float)q0.y * sc);
    hv[1] = __floats2half2_rn((float)q0.z * sc, (float)q0.w * sc);
    hv[2] = __floats2half2_rn((float)q1.x * sc, (float)q1.y * sc);
    hv[3] = __floats2half2_rn((float)q1.z * sc, (float)q1.w * sc);
    *reinterpret_cast<uint4*>(g_B + (size_t)o * D_PAD + col) = *reinterpret_cast<uint4*>(hv);
}

// ---------------- adapter GEMM: T = x @ D^T  -> g_A cols [4096,4160) ----------------
#define AD_STAGE_BYTES (2 * 64 * 128)        // A 8KB + B 8KB
#define AD_SMEM (STAGES * AD_STAGE_BYTES)    // 65536
__global__ void __launch_bounds__(128, 1) adapter_kernel() {
    extern __shared__ char smem[];
    uint32_t sbase = smem_u32(smem);
    int tid = threadIdx.x;
    int wid = tid >> 5;
    int lane = tid & 31;
    int m0 = blockIdx.x * 64;
    int wm = wid & 1;
    int wn = wid >> 1;

    auto load_stage = [&](int s, int c) {
        uint32_t st = sbase + s * AD_STAGE_BYTES;
        int k0 = c * BK;
#pragma unroll
        for (int j = 0; j < 4; ++j) {
            int t = tid + j * 128;
            int row = t >> 3, seg = t & 7;
            uint32_t so = (uint32_t)(row * 128 + ((seg ^ (row & 7)) << 4));
            cp16(st + so, g_A + (size_t)(m0 + row) * D_PAD + k0 + seg * 8);
        }
#pragma unroll
        for (int j = 0; j < 4; ++j) {
            int t = tid + j * 128;
            int row = t >> 3, seg = t & 7;
            uint32_t so = (uint32_t)(row * 128 + ((seg ^ (row & 7)) << 4));
            cp16(st + 8192 + so, g_D + (size_t)row * D_IN + k0 + seg * 8);
        }
    };

#pragma unroll
    for (int s = 0; s < STAGES - 1; ++s) { load_stage(s, s); CP_COMMIT(); }

    float acc[2][4][4] = {};
    int a_row_base = wm * 32 + (lane & 15);
    int b_row_base = wn * 32 + (lane & 15);
    int hi = lane >> 4;

    for (int c = 0; c < 64; ++c) {
        CP_WAIT2();
        __syncthreads();
        if (c + STAGES - 1 < 64) load_stage((c + STAGES - 1) & (STAGES - 1), c + STAGES - 1);
        CP_COMMIT();

        uint32_t stA = sbase + (c & (STAGES - 1)) * AD_STAGE_BYTES;
        uint32_t stB = stA + 8192;
#pragma unroll
        for (int kt = 0; kt < 4; ++kt) {
            uint32_t af[2][4];
#pragma unroll
            for (int mi = 0; mi < 2; ++mi) {
                int row = a_row_base + mi * 16;
                uint32_t chunk = (uint32_t)((kt * 2 + hi) ^ (row & 7));
                ldm_x4(af[mi][0], af[mi][1], af[mi][2], af[mi][3],
                       stA + (uint32_t)row * 128 + (chunk << 4));
            }
            uint32_t bf[4][2];
#pragma unroll
            for (int nj = 0; nj < 2; ++nj) {
                int row = b_row_base + nj * 16;
                uint32_t chunk = (uint32_t)((kt * 2 + hi) ^ (row & 7));
                uint32_t r0, r1, r2, r3;
                ldm_x4(r0, r1, r2, r3, stB + (uint32_t)row * 128 + (chunk << 4));
                bf[nj * 2][0] = r0; bf[nj * 2][1] = r2;
                bf[nj * 2 + 1][0] = r1; bf[nj * 2 + 1][1] = r3;
            }
#pragma unroll
            for (int mi = 0; mi < 2; ++mi)
#pragma unroll
                for (int ni = 0; ni < 4; ++ni)
                    mma16816(acc[mi][ni], af[mi], bf[ni]);
        }
    }

    int row0 = m0 + wm * 32 + (lane >> 2);
    int colb = wn * 32 + (lane & 3) * 2;
#pragma unroll
    for (int mi = 0; mi < 2; ++mi) {
#pragma unroll
        for (int ni = 0; ni < 4; ++ni) {
            __half2 h0 = __floats2half2_rn(acc[mi][ni][0], acc[mi][ni][1]);
            __half2 h1 = __floats2half2_rn(acc[mi][ni][2], acc[mi][ni][3]);
            *reinterpret_cast<__half2*>(
                g_A + (size_t)(row0 + mi * 16) * D_PAD + D_IN + colb + ni * 8) = h0;
            *reinterpret_cast<__half2*>(
                g_A + (size_t)(row0 + mi * 16 + 8) * D_PAD + D_IN + colb + ni * 8) = h1;
        }
    }
}

// ---------------- main GEMM (persistent CTAs) ----------------
// out[m,n] = sum_k g_A[m,k] * g_B[n,k] over K=4160; fp16 in, fp32 accum.
// BM=128, BN=256, BK=64, 4-stage cp.async rolling ACROSS tile boundaries.
// 8 warps (2x4), warp tile 64x64, fragments double-buffered, mid-chunk wait.
__global__ void __launch_bounds__(THREADS, 1) gemm_kernel(float* __restrict__ out) {
    extern __shared__ char smem[];
    uint32_t sbase = smem_u32(smem);
    int tid = threadIdx.x;
    int wid = tid >> 5;
    int lane = tid & 31;
    int bid = blockIdx.x;
    int nb = gridDim.x;

    int wm = wid & 1;   // 64-row half
    int wn = wid >> 1;  // 64-col quarter

    // tile index -> (m0, n0); band raster for L2 residency
    auto decode = [](int t, int& m0, int& n0) {
        int band = t >> 8;
        int r = t & 255;
        int n_tile = r >> 4;
        int m_tile = (band << 4) + (r & 15);
        m0 = m_tile * BM;
        n0 = n_tile * BN;
    };

    int ntiles_b = (NTILES - 1 - bid) / nb + 1;   // tiles for this block
    int total = ntiles_b * NCHUNK;

    // ---- rolling load cursor (points at next chunk to load) ----
    int li = 0, lc = 0;       // tile-seq index, chunk within tile
    int lm0, ln0;
    decode(bid, lm0, ln0);

    auto load_stage_cur = [&](int s) {
        uint32_t st = sbase + (uint32_t)s * STAGE_BYTES;
        int k0 = lc * BK;
#pragma unroll
        for (int j = 0; j < 4; ++j) {  // A: 1024 chunks
            int t = tid + j * THREADS;
            int row = t >> 3, seg = t & 7;
            uint32_t so = (uint32_t)(row * 128 + ((seg ^ (row & 7)) << 4));
            cp16(st + so, g_A + (size_t)(lm0 + row) * D_PAD + k0 + seg * 8);
        }
#pragma unroll
        for (int j = 0; j < 8; ++j) {  // B: 2048 chunks
            int t = tid + j * THREADS;
            int row = t >> 3, seg = t & 7;
            uint32_t so = (uint32_t)(row * 128 + ((seg ^ (row & 7)) << 4));
            cp16(st + A_TILE_BYTES + so, g_B + (size_t)(ln0 + row) * D_PAD + k0 + seg * 8);
        }
    };
    auto load_adv = [&]() {
        if (++lc == NCHUNK) {
            lc = 0;
            ++li;
            if (li < ntiles_b) decode(bid + li * nb, lm0, ln0);
        }
    };

    float acc[4][8][4] = {};            // [mi][ni][4]
    uint32_t af[2][4][4];               // [buf][mi][4]
    uint32_t bf[2][8][2];               // [buf][ni][2]

    int a_row_base = wm * 64 + (lane & 15);
    int b_row_base = wn * 64 + (lane & 15);
    int hi = lane >> 4;

    auto load_frags = [&](uint32_t stg, int kt, int bu) {
        uint32_t stA = stg, stB = stg + A_TILE_BYTES;
#pragma unroll
        for (int mi = 0; mi < 4; ++mi) {
            int row = a_row_base + mi * 16;
            uint32_t chunk = (uint32_t)((kt * 2 + hi) ^ (row & 7));
            ldm_x4(af[bu][mi][0], af[bu][mi][1], af[bu][mi][2], af[bu][mi][3],
                   stA + (uint32_t)row * 128 + (chunk << 4));
        }
#pragma unroll
        for (int nj = 0; nj < 4; ++nj) {
            int row = b_row_base + nj * 16;
            uint32_t chunk = (uint32_t)((kt * 2 + hi) ^ (row & 7));
            uint32_t r0, r1, r2, r3;
            ldm_x4(r0, r1, r2, r3, stB + (uint32_t)row * 128 + (chunk << 4));
            bf[bu][nj * 2][0] = r0; bf[bu][nj * 2][1] = r2;
            bf[bu][nj * 2 + 1][0] = r1; bf[bu][nj * 2 + 1][1] = r3;
        }
    };

    auto mma_all = [&](int bu) {
#pragma unroll
        for (int mi = 0; mi < 4; ++mi)
#pragma unroll
            for (int ni = 0; ni < 8; ++ni)
                mma16816(acc[mi][ni], af[bu][mi], bf[bu][ni]);
    };

    // ---- compute cursor ----
    int ci = 0, cc = 0;
    int cm0, cn0;
    decode(bid, cm0, cn0);

    // Prologue: 3 stages in flight; stage 0 ready; kt0 frags in buf0.
#pragma unroll
    for (int s = 0; s < STAGES - 1; ++s) {
        load_stage_cur(s);
        CP_COMMIT();
        load_adv();
    }
    CP_WAIT2();
    __syncthreads();
    load_frags(sbase, 0, 0);

    for (int g = 0; g < total; ++g) {
        uint32_t stC = sbase + (uint32_t)(g & (STAGES - 1)) * STAGE_BYTES;
        uint32_t stN = sbase + (uint32_t)((g + 1) & (STAGES - 1)) * STAGE_BYTES;

        // kt0: prefetch kt1 -> buf1; mma buf0
        load_frags(stC, 1, 1);
        mma_all(0);

        // kt1: prefetch kt2 -> buf0; mma buf1
        load_frags(stC, 2, 0);
        mma_all(1);

        // kt2: drain to make stage g+1 visible; refill pipeline.
        CP_WAIT1();
        __syncthreads();
        load_frags(stC, 3, 1);
        mma_all(0);
        if (li < ntiles_b) load_stage_cur((g + 3) & (STAGES - 1));
        CP_COMMIT();
        load_adv();

        // kt3: prefetch next chunk's kt0 (possibly next tile's); mma buf1
        load_frags(stN, 0, 0);
        mma_all(1);

        // Tile boundary: epilogue + acc reset; pipeline keeps rolling.
        if (++cc == NCHUNK) {
            int row0 = cm0 + wm * 64 + (lane >> 2);
            int colb = cn0 + wn * 64 + (lane & 3) * 2;
#pragma unroll
            for (int mi = 0; mi < 4; ++mi) {
#pragma unroll
                for (int ni = 0; ni < 8; ++ni) {
                    float* p0 = out + (size_t)(row0 + mi * 16) * D_OUT + colb + ni * 8;
                    float* p1 = out + (size_t)(row0 + mi * 16 + 8) * D_OUT + colb + ni * 8;
                    float2 v0 = {acc[mi][ni][0], acc[mi][ni][1]};
                    float2 v1 = {acc[mi][ni][2], acc[mi][ni][3]};
                    *reinterpret_cast<float2*>(p0) = v0;
                    *reinterpret_cast<float2*>(p1) = v1;
                    acc[mi][ni][0] = 0.f; acc[mi][ni][1] = 0.f;
                    acc[mi][ni][2] = 0.f; acc[mi][ni][3] = 0.f;
                }
            }
            cc = 0;
            ++ci;
            if (ci < ntiles_b) decode(bid + ci * nb, cm0, cn0);
        }
    }
}

// ---------------- launch ----------------
extern "C" void kernel_launch(void* const* d_in, const int* in_sizes, int n_in,
                              void* d_out, int out_size) {
    const float* x      = (const float*)d_in[0];
    const float* scales = (const float*)d_in[1];
    const float* U      = (const float*)d_in[2];
    const float* Dm     = (const float*)d_in[3];
    const int*   Q      = (const int*)d_in[4];
    float* out = (float*)d_out;

    cudaFuncSetAttribute(gemm_kernel, cudaFuncAttributeMaxDynamicSharedMemorySize, SMEM_TOTAL);
    cudaFuncSetAttribute(adapter_kernel, cudaFuncAttributeMaxDynamicSharedMemorySize, AD_SMEM);

    int nsm = 148;
    cudaDeviceGetAttribute(&nsm, cudaDevAttrMultiProcessorCount, 0);
    if (nsm > NTILES) nsm = NTILES;

    prep_a_kernel<<<N_TOK * 2, 256>>>(x);
    conv_d_kernel<<<(RANK * D_IN) / 1024, 256>>>(Dm);
    adapter_kernel<<<N_TOK / 64, 128, AD_SMEM>>>();
    prep_w_kernel<<<D_OUT * 2, 256>>>(scales, Q);
    copy_u_kernel<<<(D_OUT * RANK) / 512, 256>>>(U);
    gemm_kernel<<<nsm, THREADS, SMEM_TOTAL>>>(out);
}